// round 7
// baseline (speedup 1.0000x reference)
#include <cuda_runtime.h>

// Problem constants (from reference): B=128, S=256, D=1024, BETA=1.0
#define BB 128
#define SS 256
#define DD 1024
#define BETA_F 1.0f

#define NSM 148
#define BLOCKS_PER_SM 2
#define WARPS 4                        // warps per block (128 threads)
#define NBLOCKS (NSM * BLOCKS_PER_SM)  // 296 — one exact wave at occ=2
#define NTHREADS (WARPS * 32)          // 128
#define NWARPS_TOTAL (NBLOCKS * WARPS) // 1184
#define NROWS (SS - 2)                 // 254 interior rows per batch
#define TOTAL_ROWS (BB * NROWS)        // 32512

__device__ float g_partials[NBLOCKS];
__device__ unsigned g_ctr = 0;   // self-resetting via atomicInc wraparound

// Compute one row from (P,N); while consuming chunk j, refill it with the
// row-(r+2) prefetch. Returns relu(cur).
#define ROW_BODY(P, N)                                                        \
    do {                                                                      \
        const float tpv   = (float)b_inx[b * SS + r + 1];                     \
        const float alpha = (tpv - th) * inv_den;                             \
        const float sigma = alpha * (tt - tpv);                               \
        const float inv   = 1.0f / (2.0f * sigma * sigma);                    \
        const int rp = r + 2;                                                 \
        const bool hn = rp < r1;                                              \
        const float4* ppn = base;                                             \
        const float4* npn = base;                                             \
        if (hn) {                                                             \
            ppn = (const float4*)(bridges + ((size_t)b * SS + rp + 1) * DD);  \
            const int ni = neg_i[b * NROWS + rp];                             \
            const int nj = neg_j[b * NROWS + rp];                             \
            npn = (const float4*)(bridges + ((size_t)ni * SS + nj) * DD);     \
        }                                                                     \
        float accA = 0.0f, accBh = 0.0f, accBt = 0.0f;                        \
        _Pragma("unroll")                                                     \
        for (int j = 0; j < 8; j++) {                                         \
            const float4 pv = P[j], nv = N[j];                                \
            if (hn) {                                                         \
                P[j] = ppn[lane + j * 32];                                    \
                N[j] = npn[lane + j * 32];                                    \
            }                                                                 \
            const float4 hv = h[j], tv = tl[j];                               \
            const float dx = nv.x - pv.x, sx = nv.x + pv.x;                   \
            const float dy = nv.y - pv.y, sy = nv.y + pv.y;                   \
            const float dz = nv.z - pv.z, sz = nv.z + pv.z;                   \
            const float dw = nv.w - pv.w, sw = nv.w + pv.w;                   \
            accA  = fmaf(sx,   dx, accA);                                     \
            accBh = fmaf(hv.x, dx, accBh);                                    \
            accBt = fmaf(tv.x, dx, accBt);                                    \
            accA  = fmaf(sy,   dy, accA);                                     \
            accBh = fmaf(hv.y, dy, accBh);                                    \
            accBt = fmaf(tv.y, dy, accBt);                                    \
            accA  = fmaf(sz,   dz, accA);                                     \
            accBh = fmaf(hv.z, dz, accBh);                                    \
            accBt = fmaf(tv.z, dz, accBt);                                    \
            accA  = fmaf(sw,   dw, accA);                                     \
            accBh = fmaf(hv.w, dw, accBh);                                    \
            accBt = fmaf(tv.w, dw, accBt);                                    \
        }                                                                     \
        _Pragma("unroll")                                                     \
        for (int off = 16; off; off >>= 1) {                                  \
            accA  += __shfl_xor_sync(0xffffffffu, accA,  off);                \
            accBh += __shfl_xor_sync(0xffffffffu, accBh, off);                \
            accBt += __shfl_xor_sync(0xffffffffu, accBt, off);                \
        }                                                                     \
        const float mdot = fmaf(alpha, accBt, (1.0f - alpha) * accBh);        \
        const float diff = fmaf(-2.0f, mdot, accA);                           \
        const float cur  = fmaf(diff, inv, BETA_F);                           \
        if (cur > 0.0f) wloss += cur;                                         \
    } while (0)

// Process rows [r0, r1) of batch b, 2-row-deep software pipelined.
__device__ __forceinline__ float process_segment(
    const float* __restrict__ bridges,
    const int*   __restrict__ b_inx,
    const int*   __restrict__ neg_i,
    const int*   __restrict__ neg_j,
    int b, int r0, int r1, int lane)
{
    const float4* base = (const float4*)(bridges + (size_t)b * SS * DD);
    const float4* hp   = base;
    const float4* tp4  = base + (size_t)(SS - 1) * (DD / 4);

    float4 h[8], tl[8];
#pragma unroll
    for (int j = 0; j < 8; j++) {
        h[j]  = hp [lane + j * 32];
        tl[j] = tp4[lane + j * 32];
    }

    const float th = (float)b_inx[b * SS];
    const float tt = (float)b_inx[b * SS + SS - 1];
    const float inv_den = 1.0f / (tt - th);

    float wloss = 0.0f;

    float4 AP[8], AN[8], BP[8], BN[8];

    // prologue: rows r0 -> A, r0+1 -> B (32 LDG.128 in flight)
    {
        const float4* pp = (const float4*)(bridges + ((size_t)b * SS + r0 + 1) * DD);
        const int ni = neg_i[b * NROWS + r0];
        const int nj = neg_j[b * NROWS + r0];
        const float4* np = (const float4*)(bridges + ((size_t)ni * SS + nj) * DD);
#pragma unroll
        for (int j = 0; j < 8; j++) {
            AP[j] = pp[lane + j * 32];
            AN[j] = np[lane + j * 32];
        }
    }
    if (r0 + 1 < r1) {
        const float4* pp = (const float4*)(bridges + ((size_t)b * SS + r0 + 2) * DD);
        const int ni = neg_i[b * NROWS + r0 + 1];
        const int nj = neg_j[b * NROWS + r0 + 1];
        const float4* np = (const float4*)(bridges + ((size_t)ni * SS + nj) * DD);
#pragma unroll
        for (int j = 0; j < 8; j++) {
            BP[j] = pp[lane + j * 32];
            BN[j] = np[lane + j * 32];
        }
    }

    int r = r0;
    while (true) {
        ROW_BODY(AP, AN);            // consume A (row r), prefetch r+2 -> A
        r++;
        if (r >= r1) break;
        ROW_BODY(BP, BN);            // consume B (row r), prefetch r+2 -> B
        r++;
        if (r >= r1) break;
    }
    return wloss;
}

__global__ __launch_bounds__(NTHREADS, BLOCKS_PER_SM)
void bridge_loss_fused(const float* __restrict__ bridges,
                       const int*   __restrict__ b_inx,
                       const int*   __restrict__ neg_i,
                       const int*   __restrict__ neg_j,
                       float*       __restrict__ out)
{
    const int warp = threadIdx.x >> 5;
    const int lane = threadIdx.x & 31;
    const int gw   = blockIdx.x * WARPS + warp;   // 0..1183

    // balanced contiguous chunk of the flattened (b, r) row space
    int start = (int)(((long long)gw       * TOTAL_ROWS) / NWARPS_TOTAL);
    int end   = (int)(((long long)(gw + 1) * TOTAL_ROWS) / NWARPS_TOTAL);

    float wloss = 0.0f;
    while (start < end) {
        const int b  = start / NROWS;
        const int r0 = start - b * NROWS;
        const int r1 = min(end - b * NROWS, NROWS);
        wloss += process_segment(bridges, b_inx, neg_i, neg_j, b, r0, r1, lane);
        start = b * NROWS + r1;
    }

    __shared__ float sm[WARPS];
    __shared__ bool  amLast;
    if (lane == 0) sm[warp] = wloss;
    __syncthreads();
    if (threadIdx.x == 0) {
        float t = 0.0f;
#pragma unroll
        for (int w = 0; w < WARPS; w++) t += sm[w];
        g_partials[blockIdx.x] = t;
        __threadfence();
        unsigned old = atomicInc(&g_ctr, NBLOCKS - 1);   // wraps -> replay safe
        amLast = (old == NBLOCKS - 1);
    }
    __syncthreads();

    if (amLast) {
        __shared__ float fin[NTHREADS];
        float t = 0.0f;
#pragma unroll
        for (int k = 0; k < (NBLOCKS + NTHREADS - 1) / NTHREADS; k++) {
            const int idx = threadIdx.x + k * NTHREADS;
            if (idx < NBLOCKS) t += g_partials[idx];
        }
        fin[threadIdx.x] = t;
        __syncthreads();
#pragma unroll
        for (int st = NTHREADS / 2; st > 0; st >>= 1) {
            if ((int)threadIdx.x < st) fin[threadIdx.x] += fin[threadIdx.x + st];
            __syncthreads();
        }
        if (threadIdx.x == 0) out[0] = fin[0] / (float)BB;
    }
}

extern "C" void kernel_launch(void* const* d_in, const int* in_sizes, int n_in,
                              void* d_out, int out_size)
{
    const float* bridges = (const float*)d_in[0];
    const int*   b_inx   = (const int*)  d_in[1];
    const int*   neg_i   = (const int*)  d_in[2];
    const int*   neg_j   = (const int*)  d_in[3];

    bridge_loss_fused<<<NBLOCKS, NTHREADS>>>(bridges, b_inx, neg_i, neg_j,
                                             (float*)d_out);
}

// round 8
// speedup vs baseline: 1.0260x; 1.0260x over previous
#include <cuda_runtime.h>

// Problem constants (from reference): B=128, S=256, D=1024, BETA=1.0
#define BB 128
#define SS 256
#define DD 1024
#define BETA_F 1.0f

#define NSM 148
#define BLOCKS_PER_SM 3
#define WARPS 4                        // warps per block (128 threads)
#define NBLOCKS (NSM * BLOCKS_PER_SM)  // 444 — one exact wave at occ=3
#define NTHREADS (WARPS * 32)          // 128
#define NWARPS_TOTAL (NBLOCKS * WARPS) // 1776
#define NROWS (SS - 2)                 // 254 interior rows per batch
#define TOTAL_ROWS (BB * NROWS)        // 32512

__device__ float g_partials[NBLOCKS];
__device__ unsigned g_ctr = 0;   // self-resetting via atomicInc wraparound

// Consume row r: pos from PB, neg from NX. Prefetch pos(r+1)->PB (dist 1)
// and neg(r+2)->NX (dist 2). sh = this warp's smem head/tail (h at [0..255],
// t at [256..511]).
#define ROW_BODY(NX)                                                          \
    do {                                                                      \
        const float tpv   = (float)b_inx[b * SS + r + 1];                     \
        const float alpha = (tpv - th) * inv_den;                             \
        const float sigma = alpha * (tt - tpv);                               \
        const float inv   = 1.0f / (2.0f * sigma * sigma);                    \
        const bool hp1 = (r + 1) < r1;                                        \
        const bool hp2 = (r + 2) < r1;                                        \
        const float4* ppn = base;                                             \
        const float4* nn2 = base;                                             \
        if (hp1)                                                              \
            ppn = (const float4*)(bridges + ((size_t)b * SS + r + 2) * DD);   \
        if (hp2) {                                                            \
            const int ni = neg_i[b * NROWS + r + 2];                          \
            const int nj = neg_j[b * NROWS + r + 2];                          \
            nn2 = (const float4*)(bridges + ((size_t)ni * SS + nj) * DD);     \
        }                                                                     \
        float accA = 0.0f, accBh = 0.0f, accBt = 0.0f;                        \
        _Pragma("unroll")                                                     \
        for (int j = 0; j < 8; j++) {                                         \
            const float4 pv = PB[j], nv = NX[j];                              \
            if (hp2) NX[j] = nn2[lane + j * 32];                              \
            if (hp1) PB[j] = ppn[lane + j * 32];                              \
            const float4 hv = sh[lane + j * 32];                              \
            const float4 tv = sh[256 + lane + j * 32];                        \
            const float dx = nv.x - pv.x, sx = nv.x + pv.x;                   \
            const float dy = nv.y - pv.y, sy = nv.y + pv.y;                   \
            const float dz = nv.z - pv.z, sz = nv.z + pv.z;                   \
            const float dw = nv.w - pv.w, sw = nv.w + pv.w;                   \
            accA  = fmaf(sx,   dx, accA);                                     \
            accBh = fmaf(hv.x, dx, accBh);                                    \
            accBt = fmaf(tv.x, dx, accBt);                                    \
            accA  = fmaf(sy,   dy, accA);                                     \
            accBh = fmaf(hv.y, dy, accBh);                                    \
            accBt = fmaf(tv.y, dy, accBt);                                    \
            accA  = fmaf(sz,   dz, accA);                                     \
            accBh = fmaf(hv.z, dz, accBh);                                    \
            accBt = fmaf(tv.z, dz, accBt);                                    \
            accA  = fmaf(sw,   dw, accA);                                     \
            accBh = fmaf(hv.w, dw, accBh);                                    \
            accBt = fmaf(tv.w, dw, accBt);                                    \
        }                                                                     \
        _Pragma("unroll")                                                     \
        for (int off = 16; off; off >>= 1) {                                  \
            accA  += __shfl_xor_sync(0xffffffffu, accA,  off);                \
            accBh += __shfl_xor_sync(0xffffffffu, accBh, off);                \
            accBt += __shfl_xor_sync(0xffffffffu, accBt, off);                \
        }                                                                     \
        const float mdot = fmaf(alpha, accBt, (1.0f - alpha) * accBh);        \
        const float diff = fmaf(-2.0f, mdot, accA);                           \
        const float cur  = fmaf(diff, inv, BETA_F);                           \
        if (cur > 0.0f) wloss += cur;                                         \
    } while (0)

// Process rows [r0, r1) of batch b. P dist-1, N dist-2 pipeline.
__device__ __forceinline__ float process_segment(
    const float* __restrict__ bridges,
    const int*   __restrict__ b_inx,
    const int*   __restrict__ neg_i,
    const int*   __restrict__ neg_j,
    float4* sh,                 // this warp's 512-float4 smem (h then t)
    int b, int r0, int r1, int lane)
{
    const float4* base = (const float4*)(bridges + (size_t)b * SS * DD);
    const float4* hp   = base;
    const float4* tp4  = base + (size_t)(SS - 1) * (DD / 4);

    // stage head/tail into this warp's smem region (once per segment)
#pragma unroll
    for (int j = 0; j < 8; j++) {
        sh[lane + j * 32]       = hp [lane + j * 32];
        sh[256 + lane + j * 32] = tp4[lane + j * 32];
    }
    __syncwarp();

    const float th = (float)b_inx[b * SS];
    const float tt = (float)b_inx[b * SS + SS - 1];
    const float inv_den = 1.0f / (tt - th);

    float wloss = 0.0f;

    float4 PB[8], NA[8], NB[8];

    // prologue: pos r0 -> PB, neg r0 -> NA, neg r0+1 -> NB (24 LDG.128)
    {
        const float4* pp = (const float4*)(bridges + ((size_t)b * SS + r0 + 1) * DD);
        const int ni = neg_i[b * NROWS + r0];
        const int nj = neg_j[b * NROWS + r0];
        const float4* np = (const float4*)(bridges + ((size_t)ni * SS + nj) * DD);
#pragma unroll
        for (int j = 0; j < 8; j++) {
            PB[j] = pp[lane + j * 32];
            NA[j] = np[lane + j * 32];
        }
    }
    if (r0 + 1 < r1) {
        const int ni = neg_i[b * NROWS + r0 + 1];
        const int nj = neg_j[b * NROWS + r0 + 1];
        const float4* np = (const float4*)(bridges + ((size_t)ni * SS + nj) * DD);
#pragma unroll
        for (int j = 0; j < 8; j++)
            NB[j] = np[lane + j * 32];
    }

    int r = r0;
    while (true) {
        ROW_BODY(NA);            // row r: neg from A, prefetch neg(r+2)->A
        r++;
        if (r >= r1) break;
        ROW_BODY(NB);            // row r: neg from B, prefetch neg(r+2)->B
        r++;
        if (r >= r1) break;
    }
    return wloss;
}

__global__ __launch_bounds__(NTHREADS, BLOCKS_PER_SM)
void bridge_loss_fused(const float* __restrict__ bridges,
                       const int*   __restrict__ b_inx,
                       const int*   __restrict__ neg_i,
                       const int*   __restrict__ neg_j,
                       float*       __restrict__ out)
{
    const int warp = threadIdx.x >> 5;
    const int lane = threadIdx.x & 31;
    const int gw   = blockIdx.x * WARPS + warp;   // 0..1775

    __shared__ float4 sh_ht[WARPS][512];          // 32 KB: per-warp h(256)+t(256)
    float4* sh = sh_ht[warp];

    // balanced contiguous chunk of the flattened (b, r) row space
    int start = (int)(((long long)gw       * TOTAL_ROWS) / NWARPS_TOTAL);
    int end   = (int)(((long long)(gw + 1) * TOTAL_ROWS) / NWARPS_TOTAL);

    float wloss = 0.0f;
    while (start < end) {
        const int b  = start / NROWS;
        const int r0 = start - b * NROWS;
        const int r1 = min(end - b * NROWS, NROWS);
        wloss += process_segment(bridges, b_inx, neg_i, neg_j, sh,
                                 b, r0, r1, lane);
        start = b * NROWS + r1;
    }

    __shared__ float sm[WARPS];
    __shared__ bool  amLast;
    if (lane == 0) sm[warp] = wloss;
    __syncthreads();
    if (threadIdx.x == 0) {
        float t = 0.0f;
#pragma unroll
        for (int w = 0; w < WARPS; w++) t += sm[w];
        g_partials[blockIdx.x] = t;
        __threadfence();
        unsigned old = atomicInc(&g_ctr, NBLOCKS - 1);   // wraps -> replay safe
        amLast = (old == NBLOCKS - 1);
    }
    __syncthreads();

    if (amLast) {
        __shared__ float fin[NTHREADS];
        float t = 0.0f;
#pragma unroll
        for (int k = 0; k < (NBLOCKS + NTHREADS - 1) / NTHREADS; k++) {
            const int idx = threadIdx.x + k * NTHREADS;
            if (idx < NBLOCKS) t += g_partials[idx];
        }
        fin[threadIdx.x] = t;
        __syncthreads();
#pragma unroll
        for (int st = NTHREADS / 2; st > 0; st >>= 1) {
            if ((int)threadIdx.x < st) fin[threadIdx.x] += fin[threadIdx.x + st];
            __syncthreads();
        }
        if (threadIdx.x == 0) out[0] = fin[0] / (float)BB;
    }
}

extern "C" void kernel_launch(void* const* d_in, const int* in_sizes, int n_in,
                              void* d_out, int out_size)
{
    const float* bridges = (const float*)d_in[0];
    const int*   b_inx   = (const int*)  d_in[1];
    const int*   neg_i   = (const int*)  d_in[2];
    const int*   neg_j   = (const int*)  d_in[3];

    bridge_loss_fused<<<NBLOCKS, NTHREADS>>>(bridges, b_inx, neg_i, neg_j,
                                             (float*)d_out);
}

// round 9
// speedup vs baseline: 1.3683x; 1.3336x over previous
#include <cuda_runtime.h>

// Problem constants (from reference): B=128, S=256, D=1024, BETA=1.0
#define BB 128
#define SS 256
#define DD 1024
#define BETA_F 1.0f

#define NSM 148
#define BLOCKS_PER_SM 6
#define NTHREADS 64                    // 2 warps = 1 pair, split D
#define NBLOCKS (NSM * BLOCKS_PER_SM)  // 888 — one exact wave at occ=6
#define NROWS (SS - 2)                 // 254 interior rows per batch
#define TOTAL_ROWS (BB * NROWS)        // 32512

__device__ float g_partials[NBLOCKS];
__device__ unsigned g_ctr = 0;   // self-resetting via atomicInc wraparound

// One row: consume (PX,NX), then IMMEDIATELY issue row r+2 loads into them,
// then reduce + pair-combine. idx(j) = lane + (warp*4 + j)*32.
#define ROW_BODY(PX, NX, PAR)                                                 \
    do {                                                                      \
        const float tpv   = (float)b_inx[b * SS + r + 1];                     \
        const float alpha = (tpv - th) * inv_den;                             \
        const float sigma = alpha * (tt - tpv);                               \
        const float inv   = 1.0f / (2.0f * sigma * sigma);                    \
        float accA = 0.0f, accBh = 0.0f, accBt = 0.0f;                        \
        float4 pv0 = PX[0], nv0 = NX[0];                                      \
        float4 pv1 = PX[1], nv1 = NX[1];                                      \
        float4 pv2 = PX[2], nv2 = NX[2];                                      \
        float4 pv3 = PX[3], nv3 = NX[3];                                      \
        /* buffers consumed: issue row r+2 loads NOW (ahead of all math) */   \
        const int rp = r + 2;                                                 \
        if (rp < r1) {                                                        \
            const float4* ppn =                                               \
                (const float4*)(bridges + ((size_t)b * SS + rp + 1) * DD);    \
            const int ni = neg_i[b * NROWS + rp];                             \
            const int nj = neg_j[b * NROWS + rp];                             \
            const float4* npn =                                               \
                (const float4*)(bridges + ((size_t)ni * SS + nj) * DD);       \
            _Pragma("unroll")                                                 \
            for (int j = 0; j < 4; j++) {                                     \
                PX[j] = ppn[hoff + lane + j * 32];                            \
                NX[j] = npn[hoff + lane + j * 32];                            \
            }                                                                 \
        }                                                                     \
        CHUNK(pv0, nv0, 0); CHUNK(pv1, nv1, 1);                               \
        CHUNK(pv2, nv2, 2); CHUNK(pv3, nv3, 3);                               \
        _Pragma("unroll")                                                     \
        for (int off = 16; off; off >>= 1) {                                  \
            accA  += __shfl_xor_sync(0xffffffffu, accA,  off);                \
            accBh += __shfl_xor_sync(0xffffffffu, accBh, off);                \
            accBt += __shfl_xor_sync(0xffffffffu, accBt, off);                \
        }                                                                     \
        if (lane == 0) {                                                      \
            part[PAR][warp][0] = accA;                                        \
            part[PAR][warp][1] = accBh;                                       \
            part[PAR][warp][2] = accBt;                                       \
        }                                                                     \
        __syncthreads();                                                      \
        if (warp == 0) {                                                      \
            const float A  = part[PAR][0][0] + part[PAR][1][0];               \
            const float Bh = part[PAR][0][1] + part[PAR][1][1];               \
            const float Bt = part[PAR][0][2] + part[PAR][1][2];               \
            const float mdot = fmaf(alpha, Bt, (1.0f - alpha) * Bh);          \
            const float diff = fmaf(-2.0f, mdot, A);                          \
            const float cur  = fmaf(diff, inv, BETA_F);                       \
            if (cur > 0.0f) wloss += cur;                                     \
        }                                                                     \
    } while (0)

#define CHUNK(pv, nv, J)                                                      \
    do {                                                                      \
        const float4 hv = h[J], tv = tl[J];                                   \
        const float dx = nv.x - pv.x, sx = nv.x + pv.x;                       \
        const float dy = nv.y - pv.y, sy = nv.y + pv.y;                       \
        const float dz = nv.z - pv.z, sz = nv.z + pv.z;                       \
        const float dw = nv.w - pv.w, sw = nv.w + pv.w;                       \
        accA  = fmaf(sx,   dx, accA);                                         \
        accBh = fmaf(hv.x, dx, accBh);                                        \
        accBt = fmaf(tv.x, dx, accBt);                                        \
        accA  = fmaf(sy,   dy, accA);                                         \
        accBh = fmaf(hv.y, dy, accBh);                                        \
        accBt = fmaf(tv.y, dy, accBt);                                        \
        accA  = fmaf(sz,   dz, accA);                                         \
        accBh = fmaf(hv.z, dz, accBh);                                        \
        accBt = fmaf(tv.z, dz, accBt);                                        \
        accA  = fmaf(sw,   dw, accA);                                         \
        accBh = fmaf(hv.w, dw, accBh);                                        \
        accBt = fmaf(tv.w, dw, accBt);                                        \
    } while (0)

__global__ __launch_bounds__(NTHREADS, BLOCKS_PER_SM)
void bridge_loss_fused(const float* __restrict__ bridges,
                       const int*   __restrict__ b_inx,
                       const int*   __restrict__ neg_i,
                       const int*   __restrict__ neg_j,
                       float*       __restrict__ out)
{
    const int warp = threadIdx.x >> 5;      // D-half owned by this warp
    const int lane = threadIdx.x & 31;
    const int hoff = warp * 128;            // float4 offset of this half

    __shared__ float part[2][2][3];         // [parity][warp][A,Bh,Bt]
    __shared__ bool  amLast;

    // balanced contiguous chunk of the flattened (b, r) row space, per BLOCK
    int start = (int)(((long long)blockIdx.x       * TOTAL_ROWS) / NBLOCKS);
    int end   = (int)(((long long)(blockIdx.x + 1) * TOTAL_ROWS) / NBLOCKS);

    float wloss = 0.0f;

    while (start < end) {
        const int b  = start / NROWS;
        const int r0 = start - b * NROWS;
        const int r1 = min(end - b * NROWS, NROWS);
        start = b * NROWS + r1;

        const float4* base = (const float4*)(bridges + (size_t)b * SS * DD);
        const float4* tp4  = base + (size_t)(SS - 1) * (DD / 4);

        // this warp's halves of head/tail, register-resident
        float4 h[4], tl[4];
#pragma unroll
        for (int j = 0; j < 4; j++) {
            h[j]  = base[hoff + lane + j * 32];
            tl[j] = tp4 [hoff + lane + j * 32];
        }

        const float th = (float)b_inx[b * SS];
        const float tt = (float)b_inx[b * SS + SS - 1];
        const float inv_den = 1.0f / (tt - th);

        float4 PA[4], NA[4], PB[4], NB[4];

        // prologue: row r0 -> A, row r0+1 -> B
        {
            const float4* pp =
                (const float4*)(bridges + ((size_t)b * SS + r0 + 1) * DD);
            const int ni = neg_i[b * NROWS + r0];
            const int nj = neg_j[b * NROWS + r0];
            const float4* np =
                (const float4*)(bridges + ((size_t)ni * SS + nj) * DD);
#pragma unroll
            for (int j = 0; j < 4; j++) {
                PA[j] = pp[hoff + lane + j * 32];
                NA[j] = np[hoff + lane + j * 32];
            }
        }
        if (r0 + 1 < r1) {
            const float4* pp =
                (const float4*)(bridges + ((size_t)b * SS + r0 + 2) * DD);
            const int ni = neg_i[b * NROWS + r0 + 1];
            const int nj = neg_j[b * NROWS + r0 + 1];
            const float4* np =
                (const float4*)(bridges + ((size_t)ni * SS + nj) * DD);
#pragma unroll
            for (int j = 0; j < 4; j++) {
                PB[j] = pp[hoff + lane + j * 32];
                NB[j] = np[hoff + lane + j * 32];
            }
        }

        int r = r0;
        while (true) {
            ROW_BODY(PA, NA, 0);
            r++;
            if (r >= r1) break;
            ROW_BODY(PB, NB, 1);
            r++;
            if (r >= r1) break;
        }
    }

    // block partial = (warp0, lane0)'s wloss (all other threads hold 0 there)
    if (threadIdx.x == 0) {
        g_partials[blockIdx.x] = wloss;
        __threadfence();
        unsigned old = atomicInc(&g_ctr, NBLOCKS - 1);   // wraps -> replay safe
        amLast = (old == NBLOCKS - 1);
    }
    __syncthreads();

    if (amLast) {
        __shared__ float fin[NTHREADS];
        float t = 0.0f;
#pragma unroll
        for (int k = 0; k < (NBLOCKS + NTHREADS - 1) / NTHREADS; k++) {
            const int idx = threadIdx.x + k * NTHREADS;
            if (idx < NBLOCKS) t += g_partials[idx];
        }
        fin[threadIdx.x] = t;
        __syncthreads();
#pragma unroll
        for (int st = NTHREADS / 2; st > 0; st >>= 1) {
            if ((int)threadIdx.x < st) fin[threadIdx.x] += fin[threadIdx.x + st];
            __syncthreads();
        }
        if (threadIdx.x == 0) out[0] = fin[0] / (float)BB;
    }
}

extern "C" void kernel_launch(void* const* d_in, const int* in_sizes, int n_in,
                              void* d_out, int out_size)
{
    const float* bridges = (const float*)d_in[0];
    const int*   b_inx   = (const int*)  d_in[1];
    const int*   neg_i   = (const int*)  d_in[2];
    const int*   neg_j   = (const int*)  d_in[3];

    bridge_loss_fused<<<NBLOCKS, NTHREADS>>>(bridges, b_inx, neg_i, neg_j,
                                             (float*)d_out);
}

// round 10
// speedup vs baseline: 1.4803x; 1.0818x over previous
#include <cuda_runtime.h>

// Problem constants (from reference): B=128, S=256, D=1024, BETA=1.0
#define BB 128
#define SS 256
#define DD 1024
#define BETA_F 1.0f

#define NSM 148
#define BLOCKS_PER_SM 3
#define WARPS 4                        // warps per block (128 threads)
#define NBLOCKS (NSM * BLOCKS_PER_SM)  // 444 — one exact wave at occ=3
#define NTHREADS (WARPS * 32)          // 128
#define NWARPS_TOTAL (NBLOCKS * WARPS) // 1776
#define NROWS (SS - 2)                 // 254 interior rows per batch
#define TOTAL_ROWS (BB * NROWS)        // 32512

__device__ float g_partials[NBLOCKS];
__device__ unsigned g_ctr = 0;   // self-resetting via atomicInc wraparound

// Consume row r (pos from P, neg from NX). P refilled dist-1 (row r+1),
// NX refilled dist-2 (row r+2; NX data is 2 rows old -> never arrival-gated).
// h/t operands come from L1-resident LDGs (default policy); streaming rows
// use __ldcs so they don't evict the h/t lines.
#define ROW_BODY(NX)                                                          \
    do {                                                                      \
        const float tpv   = (float)b_inx[b * SS + r + 1];                     \
        const float alpha = (tpv - th) * inv_den;                             \
        const float sigma = alpha * (tt - tpv);                               \
        const float inv   = 1.0f / (2.0f * sigma * sigma);                    \
        const bool hp1 = (r + 1) < r1;                                        \
        const bool hp2 = (r + 2) < r1;                                        \
        const float4* ppn = base;                                             \
        const float4* npn = base;                                             \
        if (hp1)                                                              \
            ppn = (const float4*)(bridges + ((size_t)b * SS + r + 2) * DD);   \
        if (hp2) {                                                            \
            const int ni = neg_i[b * NROWS + r + 2];                          \
            const int nj = neg_j[b * NROWS + r + 2];                          \
            npn = (const float4*)(bridges + ((size_t)ni * SS + nj) * DD);     \
        }                                                                     \
        float accA = 0.0f, accBh = 0.0f, accBt = 0.0f;                        \
        _Pragma("unroll")                                                     \
        for (int j = 0; j < 8; j++) {                                         \
            const float4 pv = P[j], nv = NX[j];                               \
            if (hp2) NX[j] = __ldcs(npn + lane + j * 32);                     \
            if (hp1) P[j]  = __ldcs(ppn + lane + j * 32);                     \
            const float4 hv = hrow[lane + j * 32];                            \
            const float4 tv = trow[lane + j * 32];                            \
            const float dx = nv.x - pv.x, sx = nv.x + pv.x;                   \
            const float dy = nv.y - pv.y, sy = nv.y + pv.y;                   \
            const float dz = nv.z - pv.z, sz = nv.z + pv.z;                   \
            const float dw = nv.w - pv.w, sw = nv.w + pv.w;                   \
            accA  = fmaf(sx,   dx, accA);                                     \
            accBh = fmaf(hv.x, dx, accBh);                                    \
            accBt = fmaf(tv.x, dx, accBt);                                    \
            accA  = fmaf(sy,   dy, accA);                                     \
            accBh = fmaf(hv.y, dy, accBh);                                    \
            accBt = fmaf(tv.y, dy, accBt);                                    \
            accA  = fmaf(sz,   dz, accA);                                     \
            accBh = fmaf(hv.z, dz, accBh);                                    \
            accBt = fmaf(tv.z, dz, accBt);                                    \
            accA  = fmaf(sw,   dw, accA);                                     \
            accBh = fmaf(hv.w, dw, accBh);                                    \
            accBt = fmaf(tv.w, dw, accBt);                                    \
        }                                                                     \
        _Pragma("unroll")                                                     \
        for (int off = 16; off; off >>= 1) {                                  \
            accA  += __shfl_xor_sync(0xffffffffu, accA,  off);                \
            accBh += __shfl_xor_sync(0xffffffffu, accBh, off);                \
            accBt += __shfl_xor_sync(0xffffffffu, accBt, off);                \
        }                                                                     \
        const float mdot = fmaf(alpha, accBt, (1.0f - alpha) * accBh);        \
        const float diff = fmaf(-2.0f, mdot, accA);                           \
        const float cur  = fmaf(diff, inv, BETA_F);                           \
        if (cur > 0.0f) wloss += cur;                                         \
    } while (0)

// Process rows [r0, r1) of batch b. P dist-1, N dist-2 (double-buffered).
__device__ __forceinline__ float process_segment(
    const float* __restrict__ bridges,
    const int*   __restrict__ b_inx,
    const int*   __restrict__ neg_i,
    const int*   __restrict__ neg_j,
    int b, int r0, int r1, int lane)
{
    const float4* base = (const float4*)(bridges + (size_t)b * SS * DD);
    const float4* hrow = base;                               // h: L1-resident
    const float4* trow = base + (size_t)(SS - 1) * (DD / 4); // t: L1-resident

    const float th = (float)b_inx[b * SS];
    const float tt = (float)b_inx[b * SS + SS - 1];
    const float inv_den = 1.0f / (tt - th);

    float wloss = 0.0f;

    float4 P[8], NA[8], NB[8];

    // prologue: pos r0 -> P, neg r0 -> NA, neg r0+1 -> NB
    {
        const float4* pp = (const float4*)(bridges + ((size_t)b * SS + r0 + 1) * DD);
        const int ni = neg_i[b * NROWS + r0];
        const int nj = neg_j[b * NROWS + r0];
        const float4* np = (const float4*)(bridges + ((size_t)ni * SS + nj) * DD);
#pragma unroll
        for (int j = 0; j < 8; j++) {
            P[j]  = __ldcs(pp + lane + j * 32);
            NA[j] = __ldcs(np + lane + j * 32);
        }
    }
    if (r0 + 1 < r1) {
        const int ni = neg_i[b * NROWS + r0 + 1];
        const int nj = neg_j[b * NROWS + r0 + 1];
        const float4* np = (const float4*)(bridges + ((size_t)ni * SS + nj) * DD);
#pragma unroll
        for (int j = 0; j < 8; j++)
            NB[j] = __ldcs(np + lane + j * 32);
    }

    int r = r0;
    while (true) {
        ROW_BODY(NA);            // row r: neg from A, refill A with neg(r+2)
        r++;
        if (r >= r1) break;
        ROW_BODY(NB);            // row r: neg from B, refill B with neg(r+2)
        r++;
        if (r >= r1) break;
    }
    return wloss;
}

__global__ __launch_bounds__(NTHREADS, BLOCKS_PER_SM)
void bridge_loss_fused(const float* __restrict__ bridges,
                       const int*   __restrict__ b_inx,
                       const int*   __restrict__ neg_i,
                       const int*   __restrict__ neg_j,
                       float*       __restrict__ out)
{
    const int warp = threadIdx.x >> 5;
    const int lane = threadIdx.x & 31;
    const int gw   = blockIdx.x * WARPS + warp;   // 0..1775

    // balanced contiguous chunk of the flattened (b, r) row space
    int start = (int)(((long long)gw       * TOTAL_ROWS) / NWARPS_TOTAL);
    int end   = (int)(((long long)(gw + 1) * TOTAL_ROWS) / NWARPS_TOTAL);

    float wloss = 0.0f;
    while (start < end) {
        const int b  = start / NROWS;
        const int r0 = start - b * NROWS;
        const int r1 = min(end - b * NROWS, NROWS);
        wloss += process_segment(bridges, b_inx, neg_i, neg_j, b, r0, r1, lane);
        start = b * NROWS + r1;
    }

    __shared__ float sm[WARPS];
    __shared__ bool  amLast;
    if (lane == 0) sm[warp] = wloss;
    __syncthreads();
    if (threadIdx.x == 0) {
        float t = 0.0f;
#pragma unroll
        for (int w = 0; w < WARPS; w++) t += sm[w];
        g_partials[blockIdx.x] = t;
        __threadfence();
        unsigned old = atomicInc(&g_ctr, NBLOCKS - 1);   // wraps -> replay safe
        amLast = (old == NBLOCKS - 1);
    }
    __syncthreads();

    if (amLast) {
        __shared__ float fin[NTHREADS];
        float t = 0.0f;
#pragma unroll
        for (int k = 0; k < (NBLOCKS + NTHREADS - 1) / NTHREADS; k++) {
            const int idx = threadIdx.x + k * NTHREADS;
            if (idx < NBLOCKS) t += g_partials[idx];
        }
        fin[threadIdx.x] = t;
        __syncthreads();
#pragma unroll
        for (int st = NTHREADS / 2; st > 0; st >>= 1) {
            if ((int)threadIdx.x < st) fin[threadIdx.x] += fin[threadIdx.x + st];
            __syncthreads();
        }
        if (threadIdx.x == 0) out[0] = fin[0] / (float)BB;
    }
}

extern "C" void kernel_launch(void* const* d_in, const int* in_sizes, int n_in,
                              void* d_out, int out_size)
{
    const float* bridges = (const float*)d_in[0];
    const int*   b_inx   = (const int*)  d_in[1];
    const int*   neg_i   = (const int*)  d_in[2];
    const int*   neg_j   = (const int*)  d_in[3];

    bridge_loss_fused<<<NBLOCKS, NTHREADS>>>(bridges, b_inx, neg_i, neg_j,
                                             (float*)d_out);
}

// round 11
// speedup vs baseline: 1.4889x; 1.0058x over previous
#include <cuda_runtime.h>

// Problem constants (from reference): B=128, S=256, D=1024, BETA=1.0
#define BB 128
#define SS 256
#define DD 1024
#define BETA_F 1.0f

#define NSM 148
#define BLOCKS_PER_SM 4
#define WARPS 4                        // warps per block (128 threads)
#define NBLOCKS (NSM * BLOCKS_PER_SM)  // 592 — one exact wave at occ=4
#define NTHREADS (WARPS * 32)          // 128
#define NWARPS_TOTAL (NBLOCKS * WARPS) // 2368
#define NROWS (SS - 2)                 // 254 interior rows per batch
#define TOTAL_ROWS (BB * NROWS)        // 32512

__device__ float g_partials[NBLOCKS];
__device__ unsigned g_ctr = 0;   // self-resetting via atomicInc wraparound

// Process rows [r0, r1) of batch b. Dist-1 software pipeline on both streams;
// h/t read per-chunk from L1 (kept resident: streams use __ldcs evict-first).
__device__ __forceinline__ float process_segment(
    const float* __restrict__ bridges,
    const int*   __restrict__ b_inx,
    const int*   __restrict__ neg_i,
    const int*   __restrict__ neg_j,
    int b, int r0, int r1, int lane)
{
    const float4* base = (const float4*)(bridges + (size_t)b * SS * DD);
    const float4* hrow = base;                               // L1-resident
    const float4* trow = base + (size_t)(SS - 1) * (DD / 4); // L1-resident

    const float th = (float)b_inx[b * SS];
    const float tt = (float)b_inx[b * SS + SS - 1];
    const float inv_den = 1.0f / (tt - th);

    float wloss = 0.0f;

    float4 P[8], N[8];

    // prologue: row r0 fully in flight (16 LDG.128)
    {
        const float4* pp = (const float4*)(bridges + ((size_t)b * SS + r0 + 1) * DD);
        const int ni = neg_i[b * NROWS + r0];
        const int nj = neg_j[b * NROWS + r0];
        const float4* np = (const float4*)(bridges + ((size_t)ni * SS + nj) * DD);
#pragma unroll
        for (int j = 0; j < 8; j++) {
            P[j] = __ldcs(pp + lane + j * 32);
            N[j] = __ldcs(np + lane + j * 32);
        }
    }

    int r = r0;
    while (r < r1) {
        const float tpv   = (float)b_inx[b * SS + r + 1];
        const float alpha = (tpv - th) * inv_den;
        const float sigma = alpha * (tt - tpv);
        const float inv   = 1.0f / (2.0f * sigma * sigma);

        const int rn = r + 1;
        const bool hn = rn < r1;
        const float4* ppn = base;          // safe dummy
        const float4* npn = base;
        if (hn) {
            ppn = (const float4*)(bridges + ((size_t)b * SS + rn + 1) * DD);
            const int ni = neg_i[b * NROWS + rn];
            const int nj = neg_j[b * NROWS + rn];
            npn = (const float4*)(bridges + ((size_t)ni * SS + nj) * DD);
        }

        // A = sum (n^2 - p^2); Bh = sum h*(n-p); Bt = sum t*(n-p)
        float accA = 0.0f, accBh = 0.0f, accBt = 0.0f;
#pragma unroll
        for (int j = 0; j < 8; j++) {
            const float4 pv = P[j], nv = N[j];
            if (hn) {                      // prefetch next row, chunk j
                P[j] = __ldcs(ppn + lane + j * 32);
                N[j] = __ldcs(npn + lane + j * 32);
            }
            const float4 hv = hrow[lane + j * 32];   // L1 hit
            const float4 tv = trow[lane + j * 32];   // L1 hit
            const float dx = nv.x - pv.x, sx = nv.x + pv.x;
            const float dy = nv.y - pv.y, sy = nv.y + pv.y;
            const float dz = nv.z - pv.z, sz = nv.z + pv.z;
            const float dw = nv.w - pv.w, sw = nv.w + pv.w;
            accA  = fmaf(sx,   dx, accA);
            accBh = fmaf(hv.x, dx, accBh);
            accBt = fmaf(tv.x, dx, accBt);
            accA  = fmaf(sy,   dy, accA);
            accBh = fmaf(hv.y, dy, accBh);
            accBt = fmaf(tv.y, dy, accBt);
            accA  = fmaf(sz,   dz, accA);
            accBh = fmaf(hv.z, dz, accBh);
            accBt = fmaf(tv.z, dz, accBt);
            accA  = fmaf(sw,   dw, accA);
            accBh = fmaf(hv.w, dw, accBh);
            accBt = fmaf(tv.w, dw, accBt);
        }

#pragma unroll
        for (int off = 16; off; off >>= 1) {
            accA  += __shfl_xor_sync(0xffffffffu, accA,  off);
            accBh += __shfl_xor_sync(0xffffffffu, accBh, off);
            accBt += __shfl_xor_sync(0xffffffffu, accBt, off);
        }

        const float mdot = fmaf(alpha, accBt, (1.0f - alpha) * accBh);
        const float diff = fmaf(-2.0f, mdot, accA);
        const float cur  = fmaf(diff, inv, BETA_F);
        if (cur > 0.0f) wloss += cur;

        r = rn;
    }
    return wloss;
}

__global__ __launch_bounds__(NTHREADS, BLOCKS_PER_SM)
void bridge_loss_fused(const float* __restrict__ bridges,
                       const int*   __restrict__ b_inx,
                       const int*   __restrict__ neg_i,
                       const int*   __restrict__ neg_j,
                       float*       __restrict__ out)
{
    const int warp = threadIdx.x >> 5;
    const int lane = threadIdx.x & 31;
    const int gw   = blockIdx.x * WARPS + warp;   // 0..2367

    // balanced contiguous chunk of the flattened (b, r) row space
    int start = (int)(((long long)gw       * TOTAL_ROWS) / NWARPS_TOTAL);
    int end   = (int)(((long long)(gw + 1) * TOTAL_ROWS) / NWARPS_TOTAL);

    float wloss = 0.0f;
    while (start < end) {
        const int b  = start / NROWS;
        const int r0 = start - b * NROWS;
        const int r1 = min(end - b * NROWS, NROWS);
        wloss += process_segment(bridges, b_inx, neg_i, neg_j, b, r0, r1, lane);
        start = b * NROWS + r1;
    }

    __shared__ float sm[WARPS];
    __shared__ bool  amLast;
    if (lane == 0) sm[warp] = wloss;
    __syncthreads();
    if (threadIdx.x == 0) {
        float t = 0.0f;
#pragma unroll
        for (int w = 0; w < WARPS; w++) t += sm[w];
        g_partials[blockIdx.x] = t;
        __threadfence();
        unsigned old = atomicInc(&g_ctr, NBLOCKS - 1);   // wraps -> replay safe
        amLast = (old == NBLOCKS - 1);
    }
    __syncthreads();

    if (amLast) {
        __shared__ float fin[NTHREADS];
        float t = 0.0f;
#pragma unroll
        for (int k = 0; k < (NBLOCKS + NTHREADS - 1) / NTHREADS; k++) {
            const int idx = threadIdx.x + k * NTHREADS;
            if (idx < NBLOCKS) t += g_partials[idx];
        }
        fin[threadIdx.x] = t;
        __syncthreads();
#pragma unroll
        for (int st = NTHREADS / 2; st > 0; st >>= 1) {
            if ((int)threadIdx.x < st) fin[threadIdx.x] += fin[threadIdx.x + st];
            __syncthreads();
        }
        if (threadIdx.x == 0) out[0] = fin[0] / (float)BB;
    }
}

extern "C" void kernel_launch(void* const* d_in, const int* in_sizes, int n_in,
                              void* d_out, int out_size)
{
    const float* bridges = (const float*)d_in[0];
    const int*   b_inx   = (const int*)  d_in[1];
    const int*   neg_i   = (const int*)  d_in[2];
    const int*   neg_j   = (const int*)  d_in[3];

    bridge_loss_fused<<<NBLOCKS, NTHREADS>>>(bridges, b_inx, neg_i, neg_j,
                                             (float*)d_out);
}